// round 4
// baseline (speedup 1.0000x reference)
#include <cuda_runtime.h>
#include <math.h>

#define NB 4096
#define NT 512
#define OBS 2
#define LAT 4
#define NH 20
#define RNNH 25

typedef unsigned long long u64;

// scratch: pred_z[b][t][4]
__device__ float g_pred_z[(size_t)NB * NT * LAT];

static __device__ __forceinline__ float tanh_fast(float x) {
    float r;
    asm("tanh.approx.f32 %0, %1;" : "=f"(r) : "f"(x));
    return r;
}
static __device__ __forceinline__ float elu_fast(float x) {
    return x > 0.f ? x : (__expf(x) - 1.f);
}
static __device__ __forceinline__ u64 pack2(float lo, float hi) {
    u64 r; asm("mov.b64 %0, {%1, %2};" : "=l"(r) : "f"(lo), "f"(hi)); return r;
}
static __device__ __forceinline__ float2 unpack2(u64 v) {
    float2 r; asm("mov.b64 {%0, %1}, %2;" : "=f"(r.x), "=f"(r.y) : "l"(v)); return r;
}
static __device__ __forceinline__ u64 fma2(u64 a, u64 b, u64 c) {
    u64 d; asm("fma.rn.f32x2 %0, %1, %2, %3;" : "=l"(d) : "l"(a), "l"(b), "l"(c)); return d;
}

// ---------------- RNN: one warp per batch, smem h-exchange, f32x2 MACs ----------------
__global__ __launch_bounds__(128) void rnn_kernel(
    const float* __restrict__ trajs,   // (B,T,2)
    const float* __restrict__ eps,     // (B,4)
    const float* __restrict__ i2h_w,   // (27,25)
    const float* __restrict__ i2h_b,   // (25)
    const float* __restrict__ h2o_w,   // (25,8)
    const float* __restrict__ h2o_b,   // (8)
    float* __restrict__ out)
{
    __shared__ __align__(16) float hb[4][2][28];
    int w    = threadIdx.x >> 5;
    int lane = threadIdx.x & 31;
    int b    = blockIdx.x * 4 + w;
    int jc   = (lane < RNNH) ? lane : 0;

    if (lane < 28) { hb[w][0][lane] = 0.f; hb[w][1][lane] = 0.f; }

    // packed weights: Wx = (w_x0, w_x1); Wh[p] covers h[2p], h[2p+1]
    u64 Wx = pack2(__ldg(&i2h_w[0 * RNNH + jc]), __ldg(&i2h_w[1 * RNNH + jc]));
    u64 Wh[13];
#pragma unroll
    for (int p = 0; p < 13; p++) {
        float wlo = __ldg(&i2h_w[(2 + 2 * p) * RNNH + jc]);
        float whi = (2 * p + 1 < RNNH) ? __ldg(&i2h_w[(3 + 2 * p) * RNNH + jc]) : 0.f;
        Wh[p] = pack2(wlo, whi);
    }
    float bj = __ldg(&i2h_b[jc]);
    __syncwarp();

    const u64* xb = (const u64*)(trajs + (size_t)b * NT * OBS);  // float2 as u64
    float h = 0.f;

    for (int t = NT - 1; t >= 0; --t) {
        int pb = t & 1;
        if (lane < RNNH) hb[w][pb][lane] = h;
        u64 xp = __ldg(&xb[t]);
        __syncwarp();
        // gather 26 h values (h[25..27] stay 0 forever) as 13 packed pairs
        u64 hp[14];
        const ulonglong2* hv = (const ulonglong2*)hb[w][pb];
#pragma unroll
        for (int q = 0; q < 7; q++) { ulonglong2 v = hv[q]; hp[2 * q] = v.x; hp[2 * q + 1] = v.y; }
        u64 a0 = fma2(xp, Wx, pack2(bj, 0.f));
        u64 a1 = 0ull;
#pragma unroll
        for (int p = 0; p < 13; p += 2) a0 = fma2(hp[p], Wh[p], a0);
#pragma unroll
        for (int p = 1; p < 13; p += 2) a1 = fma2(hp[p], Wh[p], a1);
        float2 r0 = unpack2(a0), r1 = unpack2(a1);
        float acc = (r0.x + r1.x) + (r0.y + r1.y);
        h = (lane < RNNH) ? tanh_fast(acc) : 0.f;
    }

    // out8 = h_last @ h2o_w + h2o_b  (h = 0 for lanes >= 25)
    float p[2 * LAT];
#pragma unroll
    for (int i = 0; i < 2 * LAT; i++) p[i] = h * __ldg(&h2o_w[jc * (2 * LAT) + i]);
#pragma unroll
    for (int off = 16; off >= 1; off >>= 1) {
#pragma unroll
        for (int i = 0; i < 2 * LAT; i++)
            p[i] += __shfl_xor_sync(0xffffffffu, p[i], off);
    }

    if (lane == 0) {
        const size_t PX = (size_t)NB * NT * OBS;
        float z0v[LAT];
#pragma unroll
        for (int i = 0; i < LAT; i++) {
            float mean = p[i] + __ldg(&h2o_b[i]);
            float lv   = p[LAT + i] + __ldg(&h2o_b[LAT + i]);
            float z    = __ldg(&eps[b * LAT + i]) * expf(0.5f * lv) + mean;
            z0v[i] = z;
            out[PX + (size_t)b * LAT + i]                        = z;
            out[PX + (size_t)NB * LAT + (size_t)b * LAT + i]     = mean;
            out[PX + 2 * (size_t)NB * LAT + (size_t)b * LAT + i] = lv;
        }
        *(float4*)(g_pred_z + (size_t)b * NT * LAT) =
            make_float4(z0v[0], z0v[1], z0v[2], z0v[3]);
    }
}

// ---------------- ODE: 8 lanes per group, TWO batches per group ----------------
__global__ __launch_bounds__(128) void ode_kernel(
    const float* __restrict__ ts,
    const float* __restrict__ f1_w, const float* __restrict__ f1_b,   // (4,20),(20)
    const float* __restrict__ f2_w, const float* __restrict__ f2_b,   // (20,20),(20)
    const float* __restrict__ f3_w, const float* __restrict__ f3_b)   // (20,4),(4)
{
    __shared__ float dts[NT];
    __shared__ __align__(16) float uex[16][120];   // stride 120 -> conflict-free group banks

    int tid = threadIdx.x;
    for (int i = tid; i < NT - 1; i += 128) dts[i] = __ldg(&ts[i + 1]) - __ldg(&ts[i]);

    int g = tid >> 3;
    int s = tid & 7;
    int b0 = blockIdx.x * 32 + 2 * g;
    int b1 = b0 + 1;

    int jm[3]; bool vm[3];
#pragma unroll
    for (int m = 0; m < 3; m++) {
        int j = s + 8 * m;
        vm[m] = (j < NH);
        jm[m] = vm[m] ? j : 0;
    }

    float W1[LAT][3], W3[3][LAT], b1c[3], b2c[3], b3c[LAT];
    u64 W2p[3][10];
#pragma unroll
    for (int m = 0; m < 3; m++) {
#pragma unroll
        for (int i = 0; i < LAT; i++) W1[i][m] = __ldg(&f1_w[i * NH + jm[m]]);
#pragma unroll
        for (int p = 0; p < 10; p++)
            W2p[m][p] = pack2(__ldg(&f2_w[(2 * p) * NH + jm[m]]),
                              __ldg(&f2_w[(2 * p + 1) * NH + jm[m]]));
#pragma unroll
        for (int i = 0; i < LAT; i++) W3[m][i] = __ldg(&f3_w[jm[m] * LAT + i]);
        b1c[m] = __ldg(&f1_b[jm[m]]);
        b2c[m] = __ldg(&f2_b[jm[m]]);
    }
#pragma unroll
    for (int i = 0; i < LAT; i++) b3c[i] = __ldg(&f3_b[i]);

    __syncthreads();
    float* exg = uex[g];

    // fused f(z) for both batches, one sync
    auto feval2 = [&](const float* za, const float* zb, float* ka, float* kb, int pbuf) {
        int base = pbuf * 56;
        float ua[3], ub[3];
#pragma unroll
        for (int m = 0; m < 3; m++) {
            float aa = fmaf(za[0], W1[0][m], b1c[m]); float ca = za[1] * W1[1][m];
            aa = fmaf(za[2], W1[2][m], aa);           ca = fmaf(za[3], W1[3][m], ca);
            ua[m] = vm[m] ? elu_fast(aa + ca) : 0.f;
            float ab = fmaf(zb[0], W1[0][m], b1c[m]); float cb = zb[1] * W1[1][m];
            ab = fmaf(zb[2], W1[2][m], ab);           cb = fmaf(zb[3], W1[3][m], cb);
            ub[m] = vm[m] ? elu_fast(ab + cb) : 0.f;
        }
#pragma unroll
        for (int m = 0; m < 3; m++) {
            exg[base + s + 8 * m]      = ua[m];
            exg[base + 28 + s + 8 * m] = ub[m];
        }
        __syncwarp();
        // gather both u-vectors as packed pairs (5 LDS.128 each)
        u64 upa[10], upb[10];
        {
            const ulonglong2* va = (const ulonglong2*)(exg + base);
            const ulonglong2* vb = (const ulonglong2*)(exg + base + 28);
#pragma unroll
            for (int q = 0; q < 5; q++) {
                ulonglong2 x = va[q]; upa[2 * q] = x.x; upa[2 * q + 1] = x.y;
                ulonglong2 y = vb[q]; upb[2 * q] = y.x; upb[2 * q + 1] = y.y;
            }
        }
        float u2a[3], u2b[3];
#pragma unroll
        for (int m = 0; m < 3; m++) {
            u64 s0 = pack2(b2c[m], 0.f), s1 = 0ull;
            u64 t0 = pack2(b2c[m], 0.f), t1 = 0ull;
#pragma unroll
            for (int p = 0; p < 10; p += 2) {
                s0 = fma2(upa[p],     W2p[m][p],     s0);
                s1 = fma2(upa[p + 1], W2p[m][p + 1], s1);
                t0 = fma2(upb[p],     W2p[m][p],     t0);
                t1 = fma2(upb[p + 1], W2p[m][p + 1], t1);
            }
            float2 f0 = unpack2(s0), f1 = unpack2(s1);
            float2 g0 = unpack2(t0), g1 = unpack2(t1);
            u2a[m] = vm[m] ? elu_fast((f0.x + f1.x) + (f0.y + f1.y)) : 0.f;
            u2b[m] = vm[m] ? elu_fast((g0.x + g1.x) + (g0.y + g1.y)) : 0.f;
        }
        float pa[LAT], pb[LAT];
#pragma unroll
        for (int i = 0; i < LAT; i++) {
            pa[i] = fmaf(u2a[2], W3[2][i], fmaf(u2a[1], W3[1][i], u2a[0] * W3[0][i]));
            pb[i] = fmaf(u2b[2], W3[2][i], fmaf(u2b[1], W3[1][i], u2b[0] * W3[0][i]));
        }
#pragma unroll
        for (int off = 4; off >= 1; off >>= 1) {
#pragma unroll
            for (int i = 0; i < LAT; i++) {
                pa[i] += __shfl_xor_sync(0xffffffffu, pa[i], off, 8);
                pb[i] += __shfl_xor_sync(0xffffffffu, pb[i], off, 8);
            }
        }
#pragma unroll
        for (int i = 0; i < LAT; i++) { ka[i] = pa[i] + b3c[i]; kb[i] = pb[i] + b3c[i]; }
    };

    float za[LAT], zb[LAT];
    {
        float4 z0 = *(const float4*)(g_pred_z + (size_t)b0 * NT * LAT);
        float4 z1 = *(const float4*)(g_pred_z + (size_t)b1 * NT * LAT);
        za[0] = z0.x; za[1] = z0.y; za[2] = z0.z; za[3] = z0.w;
        zb[0] = z1.x; zb[1] = z1.y; zb[2] = z1.z; zb[3] = z1.w;
    }

    for (int t = 0; t < NT - 1; ++t) {
        float dt = dts[t], hdt = 0.5f * dt;
        float ka[LAT], kb[LAT], aa[LAT], ab[LAT], zta[LAT], ztb[LAT];
        feval2(za, zb, ka, kb, 0);
#pragma unroll
        for (int i = 0; i < LAT; i++) {
            aa[i] = ka[i];                    zta[i] = fmaf(hdt, ka[i], za[i]);
            ab[i] = kb[i];                    ztb[i] = fmaf(hdt, kb[i], zb[i]);
        }
        feval2(zta, ztb, ka, kb, 1);
#pragma unroll
        for (int i = 0; i < LAT; i++) {
            aa[i] = fmaf(2.f, ka[i], aa[i]);  zta[i] = fmaf(hdt, ka[i], za[i]);
            ab[i] = fmaf(2.f, kb[i], ab[i]);  ztb[i] = fmaf(hdt, kb[i], zb[i]);
        }
        feval2(zta, ztb, ka, kb, 0);
#pragma unroll
        for (int i = 0; i < LAT; i++) {
            aa[i] = fmaf(2.f, ka[i], aa[i]);  zta[i] = fmaf(dt, ka[i], za[i]);
            ab[i] = fmaf(2.f, kb[i], ab[i]);  ztb[i] = fmaf(dt, kb[i], zb[i]);
        }
        feval2(zta, ztb, ka, kb, 1);
        float c = dt * (1.f / 6.f);
#pragma unroll
        for (int i = 0; i < LAT; i++) {
            za[i] = fmaf(c, aa[i] + ka[i], za[i]);
            zb[i] = fmaf(c, ab[i] + kb[i], zb[i]);
        }
        if (s == 0) {
            *(float4*)(g_pred_z + ((size_t)b0 * NT + t + 1) * LAT) =
                make_float4(za[0], za[1], za[2], za[3]);
            *(float4*)(g_pred_z + ((size_t)b1 * NT + t + 1) * LAT) =
                make_float4(zb[0], zb[1], zb[2], zb[3]);
        }
    }
}

// ---------------- Decoder: 4 elems per thread, weights in smem ----------------
__global__ __launch_bounds__(256) void dec_kernel(
    const float* __restrict__ d1_w, const float* __restrict__ d1_b,  // (4,20),(20)
    const float* __restrict__ d2_w, const float* __restrict__ d2_b,  // (20,2),(2)
    float* __restrict__ out)
{
    __shared__ float w1s[80], b1s[20], w2s[40], b2s[2];
    int tid = threadIdx.x;
    if (tid < 80)       w1s[tid] = __ldg(&d1_w[tid]);
    else if (tid < 100) b1s[tid - 80] = __ldg(&d1_b[tid - 80]);
    else if (tid < 140) w2s[tid - 100] = __ldg(&d2_w[tid - 100]);
    else if (tid < 142) b2s[tid - 140] = __ldg(&d2_b[tid - 140]);
    __syncthreads();

    int e0 = (blockIdx.x * 256 + tid) * 4;
    float4 zv[4];
#pragma unroll
    for (int q = 0; q < 4; q++) zv[q] = *(const float4*)(g_pred_z + (size_t)(e0 + q) * LAT);

    float o0[4], o1[4];
#pragma unroll
    for (int q = 0; q < 4; q++) { o0[q] = b2s[0]; o1[q] = b2s[1]; }

#pragma unroll
    for (int j = 0; j < NH; j++) {
        float w10 = w1s[j], w11 = w1s[20 + j], w12 = w1s[40 + j], w13 = w1s[60 + j];
        float bb = b1s[j];
        float w20 = w2s[2 * j], w21 = w2s[2 * j + 1];
#pragma unroll
        for (int q = 0; q < 4; q++) {
            float hh = fmaf(zv[q].x, w10, bb);
            float h2 = zv[q].y * w11;
            hh = fmaf(zv[q].z, w12, hh);
            h2 = fmaf(zv[q].w, w13, h2);
            hh = fmaxf(hh + h2, 0.f);
            o0[q] = fmaf(hh, w20, o0[q]);
            o1[q] = fmaf(hh, w21, o1[q]);
        }
    }
    float4* op = (float4*)(out + (size_t)e0 * OBS);
    op[0] = make_float4(o0[0], o1[0], o0[1], o1[1]);
    op[1] = make_float4(o0[2], o1[2], o0[3], o1[3]);
}

extern "C" void kernel_launch(void* const* d_in, const int* in_sizes, int n_in,
                              void* d_out, int out_size)
{
    const float* trajs = (const float*)d_in[0];
    const float* ts    = (const float*)d_in[1];
    const float* eps   = (const float*)d_in[2];
    const float* i2h_w = (const float*)d_in[3];
    const float* i2h_b = (const float*)d_in[4];
    const float* h2o_w = (const float*)d_in[5];
    const float* h2o_b = (const float*)d_in[6];
    const float* f1_w  = (const float*)d_in[7];
    const float* f1_b  = (const float*)d_in[8];
    const float* f2_w  = (const float*)d_in[9];
    const float* f2_b  = (const float*)d_in[10];
    const float* f3_w  = (const float*)d_in[11];
    const float* f3_b  = (const float*)d_in[12];
    const float* d1_w  = (const float*)d_in[13];
    const float* d1_b  = (const float*)d_in[14];
    const float* d2_w  = (const float*)d_in[15];
    const float* d2_b  = (const float*)d_in[16];
    float* out = (float*)d_out;

    rnn_kernel<<<NB / 4, 128>>>(trajs, eps, i2h_w, i2h_b, h2o_w, h2o_b, out);
    ode_kernel<<<NB / 32, 128>>>(ts, f1_w, f1_b, f2_w, f2_b, f3_w, f3_b);
    dec_kernel<<<(NB * NT) / (256 * 4), 256>>>(d1_w, d1_b, d2_w, d2_b, out);
}

// round 5
// speedup vs baseline: 1.2837x; 1.2837x over previous
#include <cuda_runtime.h>
#include <math.h>

#define NB 4096
#define NT 512
#define OBS 2
#define LAT 4
#define NH 20
#define RNNH 25

typedef unsigned long long u64;

// scratch: pred_z[b][t][4]
__device__ float g_pred_z[(size_t)NB * NT * LAT];

static __device__ __forceinline__ float tanh_fast(float x) {
    float r;
    asm("tanh.approx.f32 %0, %1;" : "=f"(r) : "f"(x));
    return r;
}
static __device__ __forceinline__ float elu_fast(float x) {
    return x > 0.f ? x : (__expf(x) - 1.f);
}
static __device__ __forceinline__ u64 pack2(float lo, float hi) {
    u64 r; asm("mov.b64 %0, {%1, %2};" : "=l"(r) : "f"(lo), "f"(hi)); return r;
}
static __device__ __forceinline__ float2 unpack2(u64 v) {
    float2 r; asm("mov.b64 {%0, %1}, %2;" : "=f"(r.x), "=f"(r.y) : "l"(v)); return r;
}
static __device__ __forceinline__ u64 fma2(u64 a, u64 b, u64 c) {
    u64 d; asm("fma.rn.f32x2 %0, %1, %2, %3;" : "=l"(d) : "l"(a), "l"(b), "l"(c)); return d;
}
static __device__ __forceinline__ u64 add2(u64 a, u64 b) {
    u64 d; asm("add.rn.f32x2 %0, %1, %2;" : "=l"(d) : "l"(a), "l"(b)); return d;
}
static __device__ __forceinline__ u64 dup2(float x) { return pack2(x, x); }

// ---------------- RNN: one warp per batch, smem h-exchange, f32x2 MACs ----------------
__global__ __launch_bounds__(128) void rnn_kernel(
    const float* __restrict__ trajs,   // (B,T,2)
    const float* __restrict__ eps,     // (B,4)
    const float* __restrict__ i2h_w,   // (27,25)
    const float* __restrict__ i2h_b,   // (25)
    const float* __restrict__ h2o_w,   // (25,8)
    const float* __restrict__ h2o_b,   // (8)
    float* __restrict__ out)
{
    __shared__ __align__(16) float hb[4][2][28];
    int w    = threadIdx.x >> 5;
    int lane = threadIdx.x & 31;
    int b    = blockIdx.x * 4 + w;
    int jc   = (lane < RNNH) ? lane : 0;

    if (lane < 28) { hb[w][0][lane] = 0.f; hb[w][1][lane] = 0.f; }

    u64 Wx = pack2(__ldg(&i2h_w[0 * RNNH + jc]), __ldg(&i2h_w[1 * RNNH + jc]));
    u64 Wh[13];
#pragma unroll
    for (int p = 0; p < 13; p++) {
        float wlo = __ldg(&i2h_w[(2 + 2 * p) * RNNH + jc]);
        float whi = (2 * p + 1 < RNNH) ? __ldg(&i2h_w[(3 + 2 * p) * RNNH + jc]) : 0.f;
        Wh[p] = pack2(wlo, whi);
    }
    float bj = __ldg(&i2h_b[jc]);
    __syncwarp();

    const u64* xb = (const u64*)(trajs + (size_t)b * NT * OBS);
    float h = 0.f;

    for (int t = NT - 1; t >= 0; --t) {
        int pb = t & 1;
        if (lane < RNNH) hb[w][pb][lane] = h;
        u64 xp = __ldg(&xb[t]);
        __syncwarp();
        u64 hp[14];
        const ulonglong2* hv = (const ulonglong2*)hb[w][pb];
#pragma unroll
        for (int q = 0; q < 7; q++) { ulonglong2 v = hv[q]; hp[2 * q] = v.x; hp[2 * q + 1] = v.y; }
        u64 a0 = fma2(xp, Wx, pack2(bj, 0.f));
        u64 a1 = 0ull;
#pragma unroll
        for (int p = 0; p < 13; p += 2) a0 = fma2(hp[p], Wh[p], a0);
#pragma unroll
        for (int p = 1; p < 13; p += 2) a1 = fma2(hp[p], Wh[p], a1);
        float2 r0 = unpack2(a0), r1 = unpack2(a1);
        float acc = (r0.x + r1.x) + (r0.y + r1.y);
        h = (lane < RNNH) ? tanh_fast(acc) : 0.f;
    }

    float p[2 * LAT];
#pragma unroll
    for (int i = 0; i < 2 * LAT; i++) p[i] = h * __ldg(&h2o_w[jc * (2 * LAT) + i]);
#pragma unroll
    for (int off = 16; off >= 1; off >>= 1) {
#pragma unroll
        for (int i = 0; i < 2 * LAT; i++)
            p[i] += __shfl_xor_sync(0xffffffffu, p[i], off);
    }

    if (lane == 0) {
        const size_t PX = (size_t)NB * NT * OBS;
        float z0v[LAT];
#pragma unroll
        for (int i = 0; i < LAT; i++) {
            float mean = p[i] + __ldg(&h2o_b[i]);
            float lv   = p[LAT + i] + __ldg(&h2o_b[LAT + i]);
            float z    = __ldg(&eps[b * LAT + i]) * expf(0.5f * lv) + mean;
            z0v[i] = z;
            out[PX + (size_t)b * LAT + i]                        = z;
            out[PX + (size_t)NB * LAT + (size_t)b * LAT + i]     = mean;
            out[PX + 2 * (size_t)NB * LAT + (size_t)b * LAT + i] = lv;
        }
        *(float4*)(g_pred_z + (size_t)b * NT * LAT) =
            make_float4(z0v[0], z0v[1], z0v[2], z0v[3]);
    }
}

// ---------------- ODE: 8 lanes per batch, fully f32x2-packed ----------------
__global__ __launch_bounds__(128) void ode_kernel(
    const float* __restrict__ ts,
    const float* __restrict__ f1_w, const float* __restrict__ f1_b,   // (4,20),(20)
    const float* __restrict__ f2_w, const float* __restrict__ f2_b,   // (20,20),(20)
    const float* __restrict__ f3_w, const float* __restrict__ f3_b)   // (20,4),(4)
{
    __shared__ float dts[NT];
    __shared__ __align__(16) float uex[16][72];  // group stride 72 (mod 32 = 8): conflict-free

    int tid = threadIdx.x;
    for (int i = tid; i < NT - 1; i += 128) dts[i] = __ldg(&ts[i + 1]) - __ldg(&ts[i]);

    int g = tid >> 3;
    int s = tid & 7;
    int b = blockIdx.x * 16 + g;

    int jm[3]; bool vm[3];
#pragma unroll
    for (int m = 0; m < 3; m++) {
        int j = s + 8 * m;
        vm[m] = (j < NH);
        jm[m] = vm[m] ? j : 0;
    }

    // packed weights
    u64 W1p[3][2], W2p[3][10], W3p[3][2], b3p[2];
    float b1c[3], b2c[3];
#pragma unroll
    for (int m = 0; m < 3; m++) {
        W1p[m][0] = pack2(__ldg(&f1_w[0 * NH + jm[m]]), __ldg(&f1_w[1 * NH + jm[m]]));
        W1p[m][1] = pack2(__ldg(&f1_w[2 * NH + jm[m]]), __ldg(&f1_w[3 * NH + jm[m]]));
#pragma unroll
        for (int p = 0; p < 10; p++)
            W2p[m][p] = pack2(__ldg(&f2_w[(2 * p) * NH + jm[m]]),
                              __ldg(&f2_w[(2 * p + 1) * NH + jm[m]]));
        W3p[m][0] = pack2(__ldg(&f3_w[jm[m] * LAT + 0]), __ldg(&f3_w[jm[m] * LAT + 1]));
        W3p[m][1] = pack2(__ldg(&f3_w[jm[m] * LAT + 2]), __ldg(&f3_w[jm[m] * LAT + 3]));
        b1c[m] = __ldg(&f1_b[jm[m]]);
        b2c[m] = __ldg(&f2_b[jm[m]]);
    }
    b3p[0] = pack2(__ldg(&f3_b[0]), __ldg(&f3_b[1]));
    b3p[1] = pack2(__ldg(&f3_b[2]), __ldg(&f3_b[3]));

    __syncthreads();
    float* exg = uex[g];

    // f(z): zin/kout packed as (z0,z1),(z2,z3)
    auto feval = [&](u64 z01, u64 z23, u64& k01, u64& k23, int pbuf) {
        int base = pbuf * 32;
        float u0[3];
#pragma unroll
        for (int m = 0; m < 3; m++) {
            u64 a = fma2(z01, W1p[m][0], pack2(b1c[m], 0.f));
            a = fma2(z23, W1p[m][1], a);
            float2 f = unpack2(a);
            u0[m] = vm[m] ? elu_fast(f.x + f.y) : 0.f;
        }
        exg[base + s]      = u0[0];
        exg[base + s + 8]  = u0[1];
        exg[base + s + 16] = u0[2];
        __syncwarp();
        u64 up[10];
        {
            const ulonglong2* uv = (const ulonglong2*)(exg + base);
#pragma unroll
            for (int q = 0; q < 5; q++) { ulonglong2 v = uv[q]; up[2 * q] = v.x; up[2 * q + 1] = v.y; }
        }
        float u2[3];
#pragma unroll
        for (int m = 0; m < 3; m++) {
            u64 s0 = fma2(up[0], W2p[m][0], pack2(b2c[m], 0.f));
            u64 s1 = fma2(up[1], W2p[m][1], 0ull);
#pragma unroll
            for (int p = 2; p < 10; p += 2) {
                s0 = fma2(up[p],     W2p[m][p],     s0);
                s1 = fma2(up[p + 1], W2p[m][p + 1], s1);
            }
            float2 f = unpack2(add2(s0, s1));
            u2[m] = vm[m] ? elu_fast(f.x + f.y) : 0.f;
        }
        u64 d0 = dup2(u2[0]), d1 = dup2(u2[1]), d2 = dup2(u2[2]);
        u64 p01 = fma2(d2, W3p[2][0], fma2(d1, W3p[1][0], fma2(d0, W3p[0][0], 0ull)));
        u64 p23 = fma2(d2, W3p[2][1], fma2(d1, W3p[1][1], fma2(d0, W3p[0][1], 0ull)));
#pragma unroll
        for (int off = 4; off >= 1; off >>= 1) {
            p01 = add2(p01, __shfl_xor_sync(0xffffffffu, p01, off, 8));
            p23 = add2(p23, __shfl_xor_sync(0xffffffffu, p23, off, 8));
        }
        k01 = add2(p01, b3p[0]);
        k23 = add2(p23, b3p[1]);
    };

    u64 z01, z23;
    {
        float4 zz = *(const float4*)(g_pred_z + (size_t)b * NT * LAT);
        z01 = pack2(zz.x, zz.y);
        z23 = pack2(zz.z, zz.w);
    }
    const u64 two2 = dup2(2.f);

    for (int t = 0; t < NT - 1; ++t) {
        float dt = dts[t];
        u64 dtd  = dup2(dt);
        u64 hdtd = dup2(0.5f * dt);
        u64 cd   = dup2(dt * (1.f / 6.f));
        u64 k01, k23, a01, a23, zt01, zt23;
        feval(z01, z23, k01, k23, 0);
        a01 = k01;                       a23 = k23;
        zt01 = fma2(hdtd, k01, z01);     zt23 = fma2(hdtd, k23, z23);
        feval(zt01, zt23, k01, k23, 1);
        a01 = fma2(two2, k01, a01);      a23 = fma2(two2, k23, a23);
        zt01 = fma2(hdtd, k01, z01);     zt23 = fma2(hdtd, k23, z23);
        feval(zt01, zt23, k01, k23, 0);
        a01 = fma2(two2, k01, a01);      a23 = fma2(two2, k23, a23);
        zt01 = fma2(dtd, k01, z01);      zt23 = fma2(dtd, k23, z23);
        feval(zt01, zt23, k01, k23, 1);
        z01 = fma2(cd, add2(a01, k01), z01);
        z23 = fma2(cd, add2(a23, k23), z23);
        if (s == 0) {
            float2 lo = unpack2(z01), hi = unpack2(z23);
            *(float4*)(g_pred_z + ((size_t)b * NT + t + 1) * LAT) =
                make_float4(lo.x, lo.y, hi.x, hi.y);
        }
    }
}

// ---------------- Decoder: 4 elems per thread, weights in smem ----------------
__global__ __launch_bounds__(256) void dec_kernel(
    const float* __restrict__ d1_w, const float* __restrict__ d1_b,  // (4,20),(20)
    const float* __restrict__ d2_w, const float* __restrict__ d2_b,  // (20,2),(2)
    float* __restrict__ out)
{
    __shared__ float w1s[80], b1s[20], w2s[40], b2s[2];
    int tid = threadIdx.x;
    if (tid < 80)       w1s[tid] = __ldg(&d1_w[tid]);
    else if (tid < 100) b1s[tid - 80] = __ldg(&d1_b[tid - 80]);
    else if (tid < 140) w2s[tid - 100] = __ldg(&d2_w[tid - 100]);
    else if (tid < 142) b2s[tid - 140] = __ldg(&d2_b[tid - 140]);
    __syncthreads();

    int e0 = (blockIdx.x * 256 + tid) * 4;
    float4 zv[4];
#pragma unroll
    for (int q = 0; q < 4; q++) zv[q] = *(const float4*)(g_pred_z + (size_t)(e0 + q) * LAT);

    float o0[4], o1[4];
#pragma unroll
    for (int q = 0; q < 4; q++) { o0[q] = b2s[0]; o1[q] = b2s[1]; }

#pragma unroll
    for (int j = 0; j < NH; j++) {
        float w10 = w1s[j], w11 = w1s[20 + j], w12 = w1s[40 + j], w13 = w1s[60 + j];
        float bb = b1s[j];
        float w20 = w2s[2 * j], w21 = w2s[2 * j + 1];
#pragma unroll
        for (int q = 0; q < 4; q++) {
            float hh = fmaf(zv[q].x, w10, bb);
            float h2 = zv[q].y * w11;
            hh = fmaf(zv[q].z, w12, hh);
            h2 = fmaf(zv[q].w, w13, h2);
            hh = fmaxf(hh + h2, 0.f);
            o0[q] = fmaf(hh, w20, o0[q]);
            o1[q] = fmaf(hh, w21, o1[q]);
        }
    }
    float4* op = (float4*)(out + (size_t)e0 * OBS);
    op[0] = make_float4(o0[0], o1[0], o0[1], o1[1]);
    op[1] = make_float4(o0[2], o1[2], o0[3], o1[3]);
}

extern "C" void kernel_launch(void* const* d_in, const int* in_sizes, int n_in,
                              void* d_out, int out_size)
{
    const float* trajs = (const float*)d_in[0];
    const float* ts    = (const float*)d_in[1];
    const float* eps   = (const float*)d_in[2];
    const float* i2h_w = (const float*)d_in[3];
    const float* i2h_b = (const float*)d_in[4];
    const float* h2o_w = (const float*)d_in[5];
    const float* h2o_b = (const float*)d_in[6];
    const float* f1_w  = (const float*)d_in[7];
    const float* f1_b  = (const float*)d_in[8];
    const float* f2_w  = (const float*)d_in[9];
    const float* f2_b  = (const float*)d_in[10];
    const float* f3_w  = (const float*)d_in[11];
    const float* f3_b  = (const float*)d_in[12];
    const float* d1_w  = (const float*)d_in[13];
    const float* d1_b  = (const float*)d_in[14];
    const float* d2_w  = (const float*)d_in[15];
    const float* d2_b  = (const float*)d_in[16];
    float* out = (float*)d_out;

    rnn_kernel<<<NB / 4, 128>>>(trajs, eps, i2h_w, i2h_b, h2o_w, h2o_b, out);
    ode_kernel<<<NB / 16, 128>>>(ts, f1_w, f1_b, f2_w, f2_b, f3_w, f3_b);
    dec_kernel<<<(NB * NT) / (256 * 4), 256>>>(d1_w, d1_b, d2_w, d2_b, out);
}